// round 16
// baseline (speedup 1.0000x reference)
#include <cuda_runtime.h>
#include <cuda_fp16.h>
#include <cstdint>

#define NN 100000
#define EE 1600000
#define ET (EE + NN)
#define GG 2048
#define NBLK ((NN + 1023) / 1024)
#define WPB 8
#define XSTRH 72
#define WSTRH 72
#define WTOT 16384   // 8192 (W0) + 4096 (W1) + 4096 (W2)

typedef unsigned long long u64;

// ---------------- scratch (device globals; no allocation) ----------------
__device__ __align__(16) __half g_Hh[(size_t)NN * 64];  // fp16 transformed features
__device__ __align__(16) float  g_A[(size_t)NN * 64];   // aggregated output
__device__ __align__(16) float  g_als[NN * 4];
__device__ __align__(16) float  g_ald[NN * 4];
__device__ __align__(16) __half g_Wh[WTOT];   // fp16 hi parts of W0|W1|W2
__device__ __align__(16) __half g_Wr[WTOT];   // fp16 residuals
__device__ int g_deg[NN];       // zero-initialized at load; re-zeroed by pool_kernel
__device__ int g_scan[NN];
__device__ int g_rowptr[NN];
__device__ int g_bsum[NBLK];
__device__ int g_rank[ET];
__device__ int g_csrc[ET];

__device__ __forceinline__ float lrelu(float x) { return x > 0.f ? x : 0.2f * x; }

// ---------------- tensor-core primitives ----------------
__device__ __forceinline__ unsigned smem_u32(const void* p) {
    unsigned r;
    asm("{ .reg .u64 t; cvta.to.shared.u64 t, %1; cvt.u32.u64 %0, t; }"
        : "=r"(r) : "l"(p));
    return r;
}
__device__ __forceinline__ void ldsm_x4(unsigned& r0, unsigned& r1,
                                        unsigned& r2, unsigned& r3, unsigned a) {
    asm volatile("ldmatrix.sync.aligned.m8n8.x4.shared.b16 {%0,%1,%2,%3},[%4];"
                 : "=r"(r0), "=r"(r1), "=r"(r2), "=r"(r3) : "r"(a));
}
__device__ __forceinline__ void ldsm_x4_t(unsigned& r0, unsigned& r1,
                                          unsigned& r2, unsigned& r3, unsigned a) {
    asm volatile("ldmatrix.sync.aligned.m8n8.x4.trans.shared.b16 {%0,%1,%2,%3},[%4];"
                 : "=r"(r0), "=r"(r1), "=r"(r2), "=r"(r3) : "r"(a));
}
__device__ __forceinline__ void mma16816(float* d,
                                         unsigned a0, unsigned a1,
                                         unsigned a2, unsigned a3,
                                         unsigned b0, unsigned b1) {
    asm volatile(
        "mma.sync.aligned.m16n8k16.row.col.f32.f16.f16.f32 "
        "{%0,%1,%2,%3},{%4,%5,%6,%7},{%8,%9},{%0,%1,%2,%3};"
        : "+f"(d[0]), "+f"(d[1]), "+f"(d[2]), "+f"(d[3])
        : "r"(a0), "r"(a1), "r"(a2), "r"(a3), "r"(b0), "r"(b1));
}

// ---------------- W pre-conversion (hi + residual, once per launch) --------
__global__ void wconv_kernel(const float* __restrict__ W0,
                             const float* __restrict__ W1,
                             const float* __restrict__ W2) {
    int i = blockIdx.x * blockDim.x + threadIdx.x;
    if (i >= WTOT) return;
    float v = (i < 8192) ? W0[i] : (i < 12288) ? W1[i - 8192] : W2[i - 12288];
    __half h = __float2half_rn(v);
    g_Wh[i] = h;
    g_Wr[i] = __float2half_rn(v - __half2float(h));
}

// ---------------- CSR build (R11-verified) ----------------
__global__ void hist_kernel(const int* __restrict__ ei) {
    int i = blockIdx.x * blockDim.x + threadIdx.x;
    if (i >= ET) return;
    int dst = (i < EE) ? ei[EE + i] : (i - EE);
    g_rank[i] = atomicAdd(&g_deg[dst], 1);
}

__global__ void scan1_kernel() {
    __shared__ int wsum[32];
    int t = threadIdx.x;
    int i = blockIdx.x * 1024 + t;
    int lane = t & 31, wid = t >> 5;
    int v = (i < NN) ? g_deg[i] : 0;
    int s = v;
#pragma unroll
    for (int off = 1; off < 32; off <<= 1) {
        int u = __shfl_up_sync(0xFFFFFFFFu, s, off);
        if (lane >= off) s += u;
    }
    if (lane == 31) wsum[wid] = s;
    __syncthreads();
    if (wid == 0) {
        int ws = wsum[lane];
#pragma unroll
        for (int off = 1; off < 32; off <<= 1) {
            int u = __shfl_up_sync(0xFFFFFFFFu, ws, off);
            if (lane >= off) ws += u;
        }
        wsum[lane] = ws;
    }
    __syncthreads();
    if (wid > 0) s += wsum[wid - 1];
    if (i < NN) g_scan[i] = s;
    if (t == 1023) g_bsum[blockIdx.x] = s;
}

__global__ void scan3_kernel() {
    __shared__ int sb[128];
    __shared__ int ex[128];
    int t = threadIdx.x;
    int v0 = 0;
    if (t < 128) {
        v0 = (t < NBLK) ? g_bsum[t] : 0;
        sb[t] = v0;
    }
    __syncthreads();
    for (int off = 1; off < 128; off <<= 1) {
        int add = (t < 128 && t >= off) ? sb[t - off] : 0;
        __syncthreads();
        if (t < 128) sb[t] += add;
        __syncthreads();
    }
    if (t < 128) ex[t] = sb[t] - v0;
    __syncthreads();

    int i = blockIdx.x * blockDim.x + t;
    if (i >= NN) return;
    g_rowptr[i] = g_scan[i] - g_deg[i] + ex[i >> 10];
}

__global__ void scatter_kernel(const int* __restrict__ ei) {
    int i = blockIdx.x * blockDim.x + threadIdx.x;
    if (i >= ET) return;
    int src, dst;
    if (i < EE) { src = ei[i]; dst = ei[EE + i]; }
    else        { src = i - EE; dst = i - EE; }
    g_csrc[g_rowptr[dst] + g_rank[i]] = src;
}

// ---------------- fused GEMM + attention logits (split-precision HMMA) -----
// Block: 256 threads = 8 warps; tile 64 nodes x 64 ch; K chunks of 64.
// Warp w: node tile (w&3)*16, channel half (w>>2)*32.
// acc = Xh@Wh + Xh@Wr + Xr@Wh  (fp32-quality result from fp16 tensor cores).
template <int FIN, bool FROM_A>
__global__ void __launch_bounds__(256)
gemm_attn_kernel(const float* __restrict__ xin_ext,
                 int woff,
                 const float* __restrict__ a_src,
                 const float* __restrict__ a_dst,
                 const float* __restrict__ pbias) {
    __shared__ __align__(16) __half Xh[64 * XSTRH];
    __shared__ __align__(16) __half Xr[64 * XSTRH];
    __shared__ __align__(16) __half Whh[64 * WSTRH];
    __shared__ __align__(16) __half Whr[64 * WSTRH];
    __shared__ float Aat[128];   // [0:64) a_src, [64:128) a_dst
    __shared__ float Pb[FIN];

    int tid = threadIdx.x;
    int w = tid >> 5, L = tid & 31;
    int ntile = w & 3, nhalf = w >> 2;
    int nbase = blockIdx.x * 64;

    if (tid < 64)       Aat[tid] = a_src[tid];
    else if (tid < 128) Aat[tid] = a_dst[tid - 64];
    if (FROM_A) {
        for (int i = tid; i < FIN; i += 256) Pb[i] = pbias[i];
    }

    const float* xin = FROM_A ? (const float*)g_A : xin_ext;

    float acc[4][4];
#pragma unroll
    for (int pt = 0; pt < 4; pt++) {
#pragma unroll
        for (int j = 0; j < 4; j++) acc[pt][j] = 0.f;
    }

    // ldmatrix per-thread address components (same mapping verified in R15)
    int tile = L >> 3, trow = L & 7;
    int nodeoffA = (tile & 1) * 8 + trow;
    int koffA    = (tile >> 1) * 8;
    int krowB    = (tile & 1) * 8 + trow;
    int noffB    = (tile >> 1) * 8;

    unsigned xhb = smem_u32(Xh), xrb = smem_u32(Xr);
    unsigned whb = smem_u32(Whh), wrb = smem_u32(Whr);

    for (int ch = 0; ch < FIN / 64; ch++) {
        __syncthreads();
        // stage W chunk (pre-converted fp16, vector loads)
        for (int i = tid; i < 64 * 64 / 8; i += 256) {
            int k = (i * 8) >> 6, n = (i * 8) & 63;
            int gsrc = woff + ch * 4096 + i * 8;
            *reinterpret_cast<uint4*>(&Whh[k * WSTRH + n]) =
                *reinterpret_cast<const uint4*>(&g_Wh[gsrc]);
            *reinterpret_cast<uint4*>(&Whr[k * WSTRH + n]) =
                *reinterpret_cast<const uint4*>(&g_Wr[gsrc]);
        }
        // stage X chunk split into hi + residual
        for (int idx = tid; idx < 64 * 16; idx += 256) {
            int node = idx & 63;
            int k4 = idx >> 6;
            int gn = nbase + node;
            float4 v = make_float4(0.f, 0.f, 0.f, 0.f);
            if (gn < NN)
                v = reinterpret_cast<const float4*>(xin + (size_t)gn * FIN)[ch * 16 + k4];
            if (FROM_A) {
                v.x = fmaxf(v.x + Pb[ch * 64 + 4 * k4 + 0], 0.f);
                v.y = fmaxf(v.y + Pb[ch * 64 + 4 * k4 + 1], 0.f);
                v.z = fmaxf(v.z + Pb[ch * 64 + 4 * k4 + 2], 0.f);
                v.w = fmaxf(v.w + Pb[ch * 64 + 4 * k4 + 3], 0.f);
            }
            __half hx = __float2half_rn(v.x), hy = __float2half_rn(v.y);
            __half hz = __float2half_rn(v.z), hw2 = __float2half_rn(v.w);
            __half rx = __float2half_rn(v.x - __half2float(hx));
            __half ry = __float2half_rn(v.y - __half2float(hy));
            __half rz = __float2half_rn(v.z - __half2float(hz));
            __half rw = __float2half_rn(v.w - __half2float(hw2));
            __half2 h01 = __halves2half2(hx, hy), h23 = __halves2half2(hz, hw2);
            __half2 r01 = __halves2half2(rx, ry), r23 = __halves2half2(rz, rw);
            uint2 ph, pr;
            ph.x = *reinterpret_cast<unsigned*>(&h01);
            ph.y = *reinterpret_cast<unsigned*>(&h23);
            pr.x = *reinterpret_cast<unsigned*>(&r01);
            pr.y = *reinterpret_cast<unsigned*>(&r23);
            *reinterpret_cast<uint2*>(&Xh[node * XSTRH + k4 * 4]) = ph;
            *reinterpret_cast<uint2*>(&Xr[node * XSTRH + k4 * 4]) = pr;
        }
        __syncthreads();

#pragma unroll
        for (int ks = 0; ks < 4; ks++) {
            unsigned aoff =
                (unsigned)(((ntile * 16 + nodeoffA) * XSTRH + ks * 16 + koffA) * 2);
            unsigned ah0, ah1, ah2, ah3, ar0, ar1, ar2, ar3;
            ldsm_x4(ah0, ah1, ah2, ah3, xhb + aoff);
            ldsm_x4(ar0, ar1, ar2, ar3, xrb + aoff);
#pragma unroll
            for (int p = 0; p < 2; p++) {
                unsigned boff = (unsigned)(((ks * 16 + krowB) * WSTRH +
                                            nhalf * 32 + p * 16 + noffB) * 2);
                unsigned bh0, bh1, bh2, bh3, br0, br1, br2, br3;
                ldsm_x4_t(bh0, bh1, bh2, bh3, whb + boff);
                ldsm_x4_t(br0, br1, br2, br3, wrb + boff);
                mma16816(acc[p * 2 + 0], ah0, ah1, ah2, ah3, bh0, bh1);
                mma16816(acc[p * 2 + 1], ah0, ah1, ah2, ah3, bh2, bh3);
                mma16816(acc[p * 2 + 0], ah0, ah1, ah2, ah3, br0, br1);
                mma16816(acc[p * 2 + 1], ah0, ah1, ah2, ah3, br2, br3);
                mma16816(acc[p * 2 + 0], ar0, ar1, ar2, ar3, bh0, bh1);
                mma16816(acc[p * 2 + 1], ar0, ar1, ar2, ar3, bh2, bh3);
            }
        }
    }

    // ---- epilogue: H fp16 store + this warp's 2 heads of logits ----
    int r = L >> 2, q = L & 3;
    int node0 = nbase + ntile * 16 + r;
    int node1 = node0 + 8;
    float ss0[2] = {0.f, 0.f}, dd0[2] = {0.f, 0.f};
    float ss1[2] = {0.f, 0.f}, dd1[2] = {0.f, 0.f};

#pragma unroll
    for (int pt = 0; pt < 4; pt++) {
        int col = nhalf * 32 + pt * 8 + q * 2;
        float2 As = *reinterpret_cast<const float2*>(&Aat[col]);
        float2 Ad = *reinterpret_cast<const float2*>(&Aat[64 + col]);
        float d0 = acc[pt][0], d1 = acc[pt][1];
        float d2 = acc[pt][2], d3 = acc[pt][3];
        if (node0 < NN) {
            __half2 hv = __floats2half2_rn(d0, d1);
            *reinterpret_cast<__half2*>(&g_Hh[(size_t)node0 * 64 + col]) = hv;
        }
        if (node1 < NN) {
            __half2 hv = __floats2half2_rn(d2, d3);
            *reinterpret_cast<__half2*>(&g_Hh[(size_t)node1 * 64 + col]) = hv;
        }
        int hl = pt >> 1;
        ss0[hl] += d0 * As.x + d1 * As.y;
        dd0[hl] += d0 * Ad.x + d1 * Ad.y;
        ss1[hl] += d2 * As.x + d3 * As.y;
        dd1[hl] += d2 * Ad.x + d3 * Ad.y;
    }
#pragma unroll
    for (int hl = 0; hl < 2; hl++) {
        ss0[hl] += __shfl_xor_sync(0xFFFFFFFFu, ss0[hl], 1);
        ss0[hl] += __shfl_xor_sync(0xFFFFFFFFu, ss0[hl], 2);
        dd0[hl] += __shfl_xor_sync(0xFFFFFFFFu, dd0[hl], 1);
        dd0[hl] += __shfl_xor_sync(0xFFFFFFFFu, dd0[hl], 2);
        ss1[hl] += __shfl_xor_sync(0xFFFFFFFFu, ss1[hl], 1);
        ss1[hl] += __shfl_xor_sync(0xFFFFFFFFu, ss1[hl], 2);
        dd1[hl] += __shfl_xor_sync(0xFFFFFFFFu, dd1[hl], 1);
        dd1[hl] += __shfl_xor_sync(0xFFFFFFFFu, dd1[hl], 2);
    }
    if (q == 0) {
        int hb = nhalf * 2;
        if (node0 < NN) {
            g_als[node0 * 4 + hb + 0] = ss0[0];
            g_als[node0 * 4 + hb + 1] = ss0[1];
            g_ald[node0 * 4 + hb + 0] = dd0[0];
            g_ald[node0 * 4 + hb + 1] = dd0[1];
        }
        if (node1 < NN) {
            g_als[node1 * 4 + hb + 0] = ss1[0];
            g_als[node1 * 4 + hb + 1] = ss1[1];
            g_ald[node1 * 4 + hb + 0] = dd1[0];
            g_ald[node1 * 4 + hb + 1] = dd1[1];
        }
    }
}

// ---------------- fused softmax + aggregation (max-free, gather) -----------
__global__ void __launch_bounds__(256) gat_aggregate_kernel() {
    __shared__ int    s_s[WPB][32];
    __shared__ float4 s_w[WPB][32];

    int w = threadIdx.x >> 5;
    int lane = threadIdx.x & 31;
    int n = blockIdx.x * WPB + w;
    if (n >= NN) return;

    int beg = g_rowptr[n];
    int deg = g_deg[n];
    float4 ad = *reinterpret_cast<const float4*>(g_ald + n * 4);

    int head = lane >> 3;
    float accx = 0.f, accy = 0.f;
    float swh = 0.f;

    const __half2* Hp = reinterpret_cast<const __half2*>(g_Hh);

    if (deg <= 32) {
        if (lane < deg) {
            int s_reg = g_csrc[beg + lane];
            float4 a = *reinterpret_cast<const float4*>(g_als + s_reg * 4);
            float4 wv;
            wv.x = __expf(lrelu(a.x + ad.x));
            wv.y = __expf(lrelu(a.y + ad.y));
            wv.z = __expf(lrelu(a.z + ad.z));
            wv.w = __expf(lrelu(a.w + ad.w));
            s_s[w][lane] = s_reg;
            s_w[w][lane] = wv;
        }
        __syncwarp();

        const float* wp = reinterpret_cast<const float*>(&s_w[w][0]);
#pragma unroll 8
        for (int j = 0; j < deg; j++) {
            int s0 = s_s[w][j];
            float w0 = wp[j * 4 + head];
            swh += w0;
            float2 f = __half22float2(Hp[(size_t)s0 * 32 + lane]);
            accx = fmaf(w0, f.x, accx);
            accy = fmaf(w0, f.y, accy);
        }
    } else {
        for (int base = 0; base < deg; base += 32) {
            int i = base + lane;
            if (i < deg) {
                int s = g_csrc[beg + i];
                float4 a = *reinterpret_cast<const float4*>(g_als + s * 4);
                float4 wv;
                wv.x = __expf(lrelu(a.x + ad.x));
                wv.y = __expf(lrelu(a.y + ad.y));
                wv.z = __expf(lrelu(a.z + ad.z));
                wv.w = __expf(lrelu(a.w + ad.w));
                s_s[w][lane] = s;
                s_w[w][lane] = wv;
            }
            __syncwarp();
            int cnt = min(32, deg - base);
            const float* wp = reinterpret_cast<const float*>(&s_w[w][0]);
#pragma unroll 8
            for (int j = 0; j < cnt; j++) {
                int s0 = s_s[w][j];
                float w0 = wp[j * 4 + head];
                swh += w0;
                float2 f = __half22float2(Hp[(size_t)s0 * 32 + lane]);
                accx = fmaf(w0, f.x, accx);
                accy = fmaf(w0, f.y, accy);
            }
            __syncwarp();
        }
    }

    float inv = 1.f / (swh + 1e-16f);
    *reinterpret_cast<float2*>(g_A + (size_t)n * 64 + 2 * lane) =
        make_float2(accx * inv, accy * inv);
}

// ---------------- output init + pooling + head ----------------
__global__ void init_out_kernel(float* out, const float* __restrict__ hb) {
    int g = blockIdx.x * blockDim.x + threadIdx.x;
    if (g < GG) out[g] = hb[0];
}

__global__ void pool_kernel(const float* __restrict__ b2,
                            const float* __restrict__ hw,
                            const int* __restrict__ batch,
                            float* out) {
    __shared__ float sb[64], sw[64];
    int tid = threadIdx.x;
    if (tid < 64) { sb[tid] = b2[tid]; sw[tid] = hw[tid]; }
    __syncthreads();

    long long t = (long long)blockIdx.x * blockDim.x + tid;
    int n = (int)(t >> 5);
    int lane = (int)(t & 31);
    if (n >= NN) return;

    const float* ar = g_A + (size_t)n * 64;
    float sm = fmaxf(ar[lane] + sb[lane], 0.f) * sw[lane]
             + fmaxf(ar[lane + 32] + sb[lane + 32], 0.f) * sw[lane + 32];
#pragma unroll
    for (int off = 16; off > 0; off >>= 1)
        sm += __shfl_down_sync(0xFFFFFFFFu, sm, off);
    if (lane == 0) {
        atomicAdd(&out[batch[n]], sm);
        g_deg[n] = 0;   // restore CSR-build invariant for the next replay
    }
}

// ---------------- launch ----------------
extern "C" void kernel_launch(void* const* d_in, const int* in_sizes, int n_in,
                              void* d_out, int out_size) {
    const float* x     = (const float*)d_in[0];
    const int*   ei    = (const int*)d_in[1];
    const int*   batch = (const int*)d_in[2];
    const float* W0  = (const float*)d_in[3];
    const float* as0 = (const float*)d_in[4];
    const float* ad0 = (const float*)d_in[5];
    const float* b0  = (const float*)d_in[6];
    const float* W1  = (const float*)d_in[7];
    const float* as1 = (const float*)d_in[8];
    const float* ad1 = (const float*)d_in[9];
    const float* b1  = (const float*)d_in[10];
    const float* W2  = (const float*)d_in[11];
    const float* as2 = (const float*)d_in[12];
    const float* ad2 = (const float*)d_in[13];
    const float* b2  = (const float*)d_in[14];
    const float* hw  = (const float*)d_in[15];
    const float* hb  = (const float*)d_in[16];
    float* out = (float*)d_out;

    const int EB = (ET + 255) / 256;
    const int NB = (NN + 255) / 256;
    const int GB = (NN + 63) / 64;
    const int AB = (NN + WPB - 1) / WPB;
    const int PB = (int)(((long long)NN * 32 + 255) / 256);

    wconv_kernel<<<(WTOT + 255) / 256, 256>>>(W0, W1, W2);               // 0
    hist_kernel<<<EB, 256>>>(ei);                                        // 1
    scan1_kernel<<<NBLK, 1024>>>();                                      // 2
    gemm_attn_kernel<128, false><<<GB, 256>>>(x, 0, as0, ad0, nullptr);  // 3
    scan3_kernel<<<NB, 256>>>();                                         // 4
    scatter_kernel<<<EB, 256>>>(ei);                                     // 5

    gat_aggregate_kernel<<<AB, 256>>>();

    gemm_attn_kernel<64, true><<<GB, 256>>>(nullptr, 8192, as1, ad1, b0);
    gat_aggregate_kernel<<<AB, 256>>>();

    gemm_attn_kernel<64, true><<<GB, 256>>>(nullptr, 12288, as2, ad2, b1);
    gat_aggregate_kernel<<<AB, 256>>>();

    init_out_kernel<<<(GG + 255) / 256, 256>>>(out, hb);
    pool_kernel<<<PB, 256>>>(b2, hw, batch, out);
}

// round 17
// speedup vs baseline: 1.0251x; 1.0251x over previous
#include <cuda_runtime.h>
#include <cuda_fp16.h>
#include <cstdint>

#define NN 100000
#define EE 1600000
#define ET (EE + NN)
#define GG 2048
#define NBLK ((NN + 1023) / 1024)
#define WPB 8
#define XSTRH 72
#define WSTRH 72
#define WTOT 16384   // 8192 (W0) + 4096 (W1) + 4096 (W2)

typedef unsigned long long u64;

// ---------------- scratch (device globals; no allocation) ----------------
__device__ __align__(16) __half g_Hh[(size_t)NN * 64];  // fp16 transformed features
__device__ __align__(16) float  g_A[(size_t)NN * 64];   // aggregated output
__device__ __align__(16) float  g_als[NN * 4];
__device__ __align__(16) float  g_ald[NN * 4];
__device__ __align__(16) __half g_Wh[WTOT];   // fp16 hi parts of W0|W1|W2
__device__ __align__(16) __half g_Wr[WTOT];   // fp16 residuals
__device__ int g_deg[NN];       // zero-initialized at load; re-zeroed by pool_kernel
__device__ int g_scan[NN];
__device__ int g_rowptr[NN];
__device__ int g_bsum[NBLK];
__device__ int g_rank[ET];
__device__ int g_csrc[ET];

__device__ __forceinline__ float lrelu(float x) { return x > 0.f ? x : 0.2f * x; }

// ---------------- tensor-core primitives ----------------
__device__ __forceinline__ unsigned smem_u32(const void* p) {
    unsigned r;
    asm("{ .reg .u64 t; cvta.to.shared.u64 t, %1; cvt.u32.u64 %0, t; }"
        : "=r"(r) : "l"(p));
    return r;
}
__device__ __forceinline__ void ldsm_x4(unsigned& r0, unsigned& r1,
                                        unsigned& r2, unsigned& r3, unsigned a) {
    asm volatile("ldmatrix.sync.aligned.m8n8.x4.shared.b16 {%0,%1,%2,%3},[%4];"
                 : "=r"(r0), "=r"(r1), "=r"(r2), "=r"(r3) : "r"(a));
}
__device__ __forceinline__ void ldsm_x4_t(unsigned& r0, unsigned& r1,
                                          unsigned& r2, unsigned& r3, unsigned a) {
    asm volatile("ldmatrix.sync.aligned.m8n8.x4.trans.shared.b16 {%0,%1,%2,%3},[%4];"
                 : "=r"(r0), "=r"(r1), "=r"(r2), "=r"(r3) : "r"(a));
}
__device__ __forceinline__ void mma16816(float* d,
                                         unsigned a0, unsigned a1,
                                         unsigned a2, unsigned a3,
                                         unsigned b0, unsigned b1) {
    asm volatile(
        "mma.sync.aligned.m16n8k16.row.col.f32.f16.f16.f32 "
        "{%0,%1,%2,%3},{%4,%5,%6,%7},{%8,%9},{%0,%1,%2,%3};"
        : "+f"(d[0]), "+f"(d[1]), "+f"(d[2]), "+f"(d[3])
        : "r"(a0), "r"(a1), "r"(a2), "r"(a3), "r"(b0), "r"(b1));
}

// ---------------- W pre-conversion (hi + residual, once per launch) --------
__global__ void wconv_kernel(const float* __restrict__ W0,
                             const float* __restrict__ W1,
                             const float* __restrict__ W2) {
    int i = blockIdx.x * blockDim.x + threadIdx.x;
    if (i >= WTOT) return;
    float v = (i < 8192) ? W0[i] : (i < 12288) ? W1[i - 8192] : W2[i - 12288];
    __half h = __float2half_rn(v);
    g_Wh[i] = h;
    g_Wr[i] = __float2half_rn(v - __half2float(h));
}

// ---------------- CSR build (R11-verified) ----------------
__global__ void hist_kernel(const int* __restrict__ ei) {
    int i = blockIdx.x * blockDim.x + threadIdx.x;
    if (i >= ET) return;
    int dst = (i < EE) ? ei[EE + i] : (i - EE);
    g_rank[i] = atomicAdd(&g_deg[dst], 1);
}

__global__ void scan1_kernel() {
    __shared__ int wsum[32];
    int t = threadIdx.x;
    int i = blockIdx.x * 1024 + t;
    int lane = t & 31, wid = t >> 5;
    int v = (i < NN) ? g_deg[i] : 0;
    int s = v;
#pragma unroll
    for (int off = 1; off < 32; off <<= 1) {
        int u = __shfl_up_sync(0xFFFFFFFFu, s, off);
        if (lane >= off) s += u;
    }
    if (lane == 31) wsum[wid] = s;
    __syncthreads();
    if (wid == 0) {
        int ws = wsum[lane];
#pragma unroll
        for (int off = 1; off < 32; off <<= 1) {
            int u = __shfl_up_sync(0xFFFFFFFFu, ws, off);
            if (lane >= off) ws += u;
        }
        wsum[lane] = ws;
    }
    __syncthreads();
    if (wid > 0) s += wsum[wid - 1];
    if (i < NN) g_scan[i] = s;
    if (t == 1023) g_bsum[blockIdx.x] = s;
}

__global__ void scan3_kernel() {
    __shared__ int sb[128];
    __shared__ int ex[128];
    int t = threadIdx.x;
    int v0 = 0;
    if (t < 128) {
        v0 = (t < NBLK) ? g_bsum[t] : 0;
        sb[t] = v0;
    }
    __syncthreads();
    for (int off = 1; off < 128; off <<= 1) {
        int add = (t < 128 && t >= off) ? sb[t - off] : 0;
        __syncthreads();
        if (t < 128) sb[t] += add;
        __syncthreads();
    }
    if (t < 128) ex[t] = sb[t] - v0;
    __syncthreads();

    int i = blockIdx.x * blockDim.x + t;
    if (i >= NN) return;
    g_rowptr[i] = g_scan[i] - g_deg[i] + ex[i >> 10];
}

__global__ void scatter_kernel(const int* __restrict__ ei) {
    int i = blockIdx.x * blockDim.x + threadIdx.x;
    if (i >= ET) return;
    int src, dst;
    if (i < EE) { src = ei[i]; dst = ei[EE + i]; }
    else        { src = i - EE; dst = i - EE; }
    g_csrc[g_rowptr[dst] + g_rank[i]] = src;
}

// ---------------- fused GEMM + attention logits (split-precision HMMA) -----
template <int FIN, bool FROM_A>
__global__ void __launch_bounds__(256)
gemm_attn_kernel(const float* __restrict__ xin_ext,
                 int woff,
                 const float* __restrict__ a_src,
                 const float* __restrict__ a_dst,
                 const float* __restrict__ pbias) {
    __shared__ __align__(16) __half Xh[64 * XSTRH];
    __shared__ __align__(16) __half Xr[64 * XSTRH];
    __shared__ __align__(16) __half Whh[64 * WSTRH];
    __shared__ __align__(16) __half Whr[64 * WSTRH];
    __shared__ float Aat[128];
    __shared__ float Pb[FIN];

    int tid = threadIdx.x;
    int w = tid >> 5, L = tid & 31;
    int ntile = w & 3, nhalf = w >> 2;
    int nbase = blockIdx.x * 64;

    if (tid < 64)       Aat[tid] = a_src[tid];
    else if (tid < 128) Aat[tid] = a_dst[tid - 64];
    if (FROM_A) {
        for (int i = tid; i < FIN; i += 256) Pb[i] = pbias[i];
    }

    const float* xin = FROM_A ? (const float*)g_A : xin_ext;

    float acc[4][4];
#pragma unroll
    for (int pt = 0; pt < 4; pt++) {
#pragma unroll
        for (int j = 0; j < 4; j++) acc[pt][j] = 0.f;
    }

    int tile = L >> 3, trow = L & 7;
    int nodeoffA = (tile & 1) * 8 + trow;
    int koffA    = (tile >> 1) * 8;
    int krowB    = (tile & 1) * 8 + trow;
    int noffB    = (tile >> 1) * 8;

    unsigned xhb = smem_u32(Xh), xrb = smem_u32(Xr);
    unsigned whb = smem_u32(Whh), wrb = smem_u32(Whr);

    for (int ch = 0; ch < FIN / 64; ch++) {
        __syncthreads();
        for (int i = tid; i < 64 * 64 / 8; i += 256) {
            int k = (i * 8) >> 6, n = (i * 8) & 63;
            int gsrc = woff + ch * 4096 + i * 8;
            *reinterpret_cast<uint4*>(&Whh[k * WSTRH + n]) =
                *reinterpret_cast<const uint4*>(&g_Wh[gsrc]);
            *reinterpret_cast<uint4*>(&Whr[k * WSTRH + n]) =
                *reinterpret_cast<const uint4*>(&g_Wr[gsrc]);
        }
        for (int idx = tid; idx < 64 * 16; idx += 256) {
            int node = idx & 63;
            int k4 = idx >> 6;
            int gn = nbase + node;
            float4 v = make_float4(0.f, 0.f, 0.f, 0.f);
            if (gn < NN)
                v = reinterpret_cast<const float4*>(xin + (size_t)gn * FIN)[ch * 16 + k4];
            if (FROM_A) {
                v.x = fmaxf(v.x + Pb[ch * 64 + 4 * k4 + 0], 0.f);
                v.y = fmaxf(v.y + Pb[ch * 64 + 4 * k4 + 1], 0.f);
                v.z = fmaxf(v.z + Pb[ch * 64 + 4 * k4 + 2], 0.f);
                v.w = fmaxf(v.w + Pb[ch * 64 + 4 * k4 + 3], 0.f);
            }
            __half hx = __float2half_rn(v.x), hy = __float2half_rn(v.y);
            __half hz = __float2half_rn(v.z), hw2 = __float2half_rn(v.w);
            __half rx = __float2half_rn(v.x - __half2float(hx));
            __half ry = __float2half_rn(v.y - __half2float(hy));
            __half rz = __float2half_rn(v.z - __half2float(hz));
            __half rw = __float2half_rn(v.w - __half2float(hw2));
            __half2 h01 = __halves2half2(hx, hy), h23 = __halves2half2(hz, hw2);
            __half2 r01 = __halves2half2(rx, ry), r23 = __halves2half2(rz, rw);
            uint2 ph, pr;
            ph.x = *reinterpret_cast<unsigned*>(&h01);
            ph.y = *reinterpret_cast<unsigned*>(&h23);
            pr.x = *reinterpret_cast<unsigned*>(&r01);
            pr.y = *reinterpret_cast<unsigned*>(&r23);
            *reinterpret_cast<uint2*>(&Xh[node * XSTRH + k4 * 4]) = ph;
            *reinterpret_cast<uint2*>(&Xr[node * XSTRH + k4 * 4]) = pr;
        }
        __syncthreads();

#pragma unroll
        for (int ks = 0; ks < 4; ks++) {
            unsigned aoff =
                (unsigned)(((ntile * 16 + nodeoffA) * XSTRH + ks * 16 + koffA) * 2);
            unsigned ah0, ah1, ah2, ah3, ar0, ar1, ar2, ar3;
            ldsm_x4(ah0, ah1, ah2, ah3, xhb + aoff);
            ldsm_x4(ar0, ar1, ar2, ar3, xrb + aoff);
#pragma unroll
            for (int p = 0; p < 2; p++) {
                unsigned boff = (unsigned)(((ks * 16 + krowB) * WSTRH +
                                            nhalf * 32 + p * 16 + noffB) * 2);
                unsigned bh0, bh1, bh2, bh3, br0, br1, br2, br3;
                ldsm_x4_t(bh0, bh1, bh2, bh3, whb + boff);
                ldsm_x4_t(br0, br1, br2, br3, wrb + boff);
                mma16816(acc[p * 2 + 0], ah0, ah1, ah2, ah3, bh0, bh1);
                mma16816(acc[p * 2 + 1], ah0, ah1, ah2, ah3, bh2, bh3);
                mma16816(acc[p * 2 + 0], ah0, ah1, ah2, ah3, br0, br1);
                mma16816(acc[p * 2 + 1], ah0, ah1, ah2, ah3, br2, br3);
                mma16816(acc[p * 2 + 0], ar0, ar1, ar2, ar3, bh0, bh1);
                mma16816(acc[p * 2 + 1], ar0, ar1, ar2, ar3, bh2, bh3);
            }
        }
    }

    // ---- epilogue: H fp16 store + this warp's 2 heads of logits ----
    int r = L >> 2, q = L & 3;
    int node0 = nbase + ntile * 16 + r;
    int node1 = node0 + 8;
    float ss0[2] = {0.f, 0.f}, dd0[2] = {0.f, 0.f};
    float ss1[2] = {0.f, 0.f}, dd1[2] = {0.f, 0.f};

#pragma unroll
    for (int pt = 0; pt < 4; pt++) {
        int col = nhalf * 32 + pt * 8 + q * 2;
        float2 As = *reinterpret_cast<const float2*>(&Aat[col]);
        float2 Ad = *reinterpret_cast<const float2*>(&Aat[64 + col]);
        float d0 = acc[pt][0], d1 = acc[pt][1];
        float d2 = acc[pt][2], d3 = acc[pt][3];
        if (node0 < NN) {
            __half2 hv = __floats2half2_rn(d0, d1);
            *reinterpret_cast<__half2*>(&g_Hh[(size_t)node0 * 64 + col]) = hv;
        }
        if (node1 < NN) {
            __half2 hv = __floats2half2_rn(d2, d3);
            *reinterpret_cast<__half2*>(&g_Hh[(size_t)node1 * 64 + col]) = hv;
        }
        int hl = pt >> 1;
        ss0[hl] += d0 * As.x + d1 * As.y;
        dd0[hl] += d0 * Ad.x + d1 * Ad.y;
        ss1[hl] += d2 * As.x + d3 * As.y;
        dd1[hl] += d2 * Ad.x + d3 * Ad.y;
    }
#pragma unroll
    for (int hl = 0; hl < 2; hl++) {
        ss0[hl] += __shfl_xor_sync(0xFFFFFFFFu, ss0[hl], 1);
        ss0[hl] += __shfl_xor_sync(0xFFFFFFFFu, ss0[hl], 2);
        dd0[hl] += __shfl_xor_sync(0xFFFFFFFFu, dd0[hl], 1);
        dd0[hl] += __shfl_xor_sync(0xFFFFFFFFu, dd0[hl], 2);
        ss1[hl] += __shfl_xor_sync(0xFFFFFFFFu, ss1[hl], 1);
        ss1[hl] += __shfl_xor_sync(0xFFFFFFFFu, ss1[hl], 2);
        dd1[hl] += __shfl_xor_sync(0xFFFFFFFFu, dd1[hl], 1);
        dd1[hl] += __shfl_xor_sync(0xFFFFFFFFu, dd1[hl], 2);
    }
    if (q == 0) {
        int hb = nhalf * 2;
        if (node0 < NN) {
            g_als[node0 * 4 + hb + 0] = ss0[0];
            g_als[node0 * 4 + hb + 1] = ss0[1];
            g_ald[node0 * 4 + hb + 0] = dd0[0];
            g_ald[node0 * 4 + hb + 1] = dd0[1];
        }
        if (node1 < NN) {
            g_als[node1 * 4 + hb + 0] = ss1[0];
            g_als[node1 * 4 + hb + 1] = ss1[1];
            g_ald[node1 * 4 + hb + 0] = dd1[0];
            g_ald[node1 * 4 + hb + 1] = dd1[1];
        }
    }
}

// ---------------- fused softmax + aggregation (max-free, gather) -----------
__global__ void __launch_bounds__(256) gat_aggregate_kernel() {
    __shared__ int    s_s[WPB][32];
    __shared__ float4 s_w[WPB][32];

    int w = threadIdx.x >> 5;
    int lane = threadIdx.x & 31;
    int n = blockIdx.x * WPB + w;
    if (n >= NN) return;

    int beg = g_rowptr[n];
    int deg = g_deg[n];
    float4 ad = *reinterpret_cast<const float4*>(g_ald + n * 4);

    int head = lane >> 3;
    float accx = 0.f, accy = 0.f;
    float swh = 0.f;

    const __half2* Hp = reinterpret_cast<const __half2*>(g_Hh);

    if (deg <= 32) {
        if (lane < deg) {
            int s_reg = g_csrc[beg + lane];
            float4 a = *reinterpret_cast<const float4*>(g_als + s_reg * 4);
            float4 wv;
            wv.x = __expf(lrelu(a.x + ad.x));
            wv.y = __expf(lrelu(a.y + ad.y));
            wv.z = __expf(lrelu(a.z + ad.z));
            wv.w = __expf(lrelu(a.w + ad.w));
            s_s[w][lane] = s_reg;
            s_w[w][lane] = wv;
        }
        __syncwarp();

        const float* wp = reinterpret_cast<const float*>(&s_w[w][0]);
#pragma unroll 8
        for (int j = 0; j < deg; j++) {
            int s0 = s_s[w][j];
            float w0 = wp[j * 4 + head];
            swh += w0;
            float2 f = __half22float2(Hp[(size_t)s0 * 32 + lane]);
            accx = fmaf(w0, f.x, accx);
            accy = fmaf(w0, f.y, accy);
        }
    } else {
        for (int base = 0; base < deg; base += 32) {
            int i = base + lane;
            if (i < deg) {
                int s = g_csrc[beg + i];
                float4 a = *reinterpret_cast<const float4*>(g_als + s * 4);
                float4 wv;
                wv.x = __expf(lrelu(a.x + ad.x));
                wv.y = __expf(lrelu(a.y + ad.y));
                wv.z = __expf(lrelu(a.z + ad.z));
                wv.w = __expf(lrelu(a.w + ad.w));
                s_s[w][lane] = s;
                s_w[w][lane] = wv;
            }
            __syncwarp();
            int cnt = min(32, deg - base);
            const float* wp = reinterpret_cast<const float*>(&s_w[w][0]);
#pragma unroll 8
            for (int j = 0; j < cnt; j++) {
                int s0 = s_s[w][j];
                float w0 = wp[j * 4 + head];
                swh += w0;
                float2 f = __half22float2(Hp[(size_t)s0 * 32 + lane]);
                accx = fmaf(w0, f.x, accx);
                accy = fmaf(w0, f.y, accy);
            }
            __syncwarp();
        }
    }

    float inv = 1.f / (swh + 1e-16f);
    *reinterpret_cast<float2*>(g_A + (size_t)n * 64 + 2 * lane) =
        make_float2(accx * inv, accy * inv);
}

// ---------------- output init + pooling + head ----------------
__global__ void init_out_kernel(float* out, const float* __restrict__ hb) {
    int g = blockIdx.x * blockDim.x + threadIdx.x;
    if (g < GG) out[g] = hb[0];
}

__global__ void pool_kernel(const float* __restrict__ b2,
                            const float* __restrict__ hw,
                            const int* __restrict__ batch,
                            float* out) {
    __shared__ float sb[64], sw[64];
    int tid = threadIdx.x;
    if (tid < 64) { sb[tid] = b2[tid]; sw[tid] = hw[tid]; }
    __syncthreads();

    long long t = (long long)blockIdx.x * blockDim.x + tid;
    int n = (int)(t >> 5);
    int lane = (int)(t & 31);
    if (n >= NN) return;

    const float* ar = g_A + (size_t)n * 64;
    float sm = fmaxf(ar[lane] + sb[lane], 0.f) * sw[lane]
             + fmaxf(ar[lane + 32] + sb[lane + 32], 0.f) * sw[lane + 32];
#pragma unroll
    for (int off = 16; off > 0; off >>= 1)
        sm += __shfl_down_sync(0xFFFFFFFFu, sm, off);
    if (lane == 0) {
        atomicAdd(&out[batch[n]], sm);
        g_deg[n] = 0;   // restore CSR-build invariant for the next replay
    }
}

// ---------------- launch (fork/join: CSR build || wconv+gemm0) -------------
extern "C" void kernel_launch(void* const* d_in, const int* in_sizes, int n_in,
                              void* d_out, int out_size) {
    const float* x     = (const float*)d_in[0];
    const int*   ei    = (const int*)d_in[1];
    const int*   batch = (const int*)d_in[2];
    const float* W0  = (const float*)d_in[3];
    const float* as0 = (const float*)d_in[4];
    const float* ad0 = (const float*)d_in[5];
    const float* b0  = (const float*)d_in[6];
    const float* W1  = (const float*)d_in[7];
    const float* as1 = (const float*)d_in[8];
    const float* ad1 = (const float*)d_in[9];
    const float* b1  = (const float*)d_in[10];
    const float* W2  = (const float*)d_in[11];
    const float* as2 = (const float*)d_in[12];
    const float* ad2 = (const float*)d_in[13];
    const float* b2  = (const float*)d_in[14];
    const float* hw  = (const float*)d_in[15];
    const float* hb  = (const float*)d_in[16];
    float* out = (float*)d_out;

    const int EB = (ET + 255) / 256;
    const int NB = (NN + 255) / 256;
    const int GB = (NN + 63) / 64;
    const int AB = (NN + WPB - 1) / WPB;
    const int PB = (int)(((long long)NN * 32 + 255) / 256);

    cudaStream_t sA, sB;
    cudaStreamCreateWithFlags(&sA, cudaStreamNonBlocking);
    cudaStreamCreateWithFlags(&sB, cudaStreamNonBlocking);
    cudaEvent_t eFork, eA, eB;
    cudaEventCreateWithFlags(&eFork, cudaEventDisableTiming);
    cudaEventCreateWithFlags(&eA, cudaEventDisableTiming);
    cudaEventCreateWithFlags(&eB, cudaEventDisableTiming);

    // fork from the capture (default) stream
    cudaEventRecord(eFork, 0);
    cudaStreamWaitEvent(sA, eFork, 0);
    cudaStreamWaitEvent(sB, eFork, 0);

    // branch A: W conversion -> layer-0 GEMM (independent of CSR)
    wconv_kernel<<<(WTOT + 255) / 256, 256, 0, sA>>>(W0, W1, W2);
    gemm_attn_kernel<128, false><<<GB, 256, 0, sA>>>(x, 0, as0, ad0, nullptr);

    // branch B: CSR build
    hist_kernel<<<EB, 256, 0, sB>>>(ei);
    scan1_kernel<<<NBLK, 1024, 0, sB>>>();
    scan3_kernel<<<NB, 256, 0, sB>>>();
    scatter_kernel<<<EB, 256, 0, sB>>>(ei);

    // join both branches back into the default stream
    cudaEventRecord(eA, sA);
    cudaEventRecord(eB, sB);
    cudaStreamWaitEvent(0, eA, 0);
    cudaStreamWaitEvent(0, eB, 0);

    // sequential remainder on the default stream
    gat_aggregate_kernel<<<AB, 256>>>();

    gemm_attn_kernel<64, true><<<GB, 256>>>(nullptr, 8192, as1, ad1, b0);
    gat_aggregate_kernel<<<AB, 256>>>();

    gemm_attn_kernel<64, true><<<GB, 256>>>(nullptr, 12288, as2, ad2, b1);
    gat_aggregate_kernel<<<AB, 256>>>();

    init_out_kernel<<<(GG + 255) / 256, 256>>>(out, hb);
    pool_kernel<<<PB, 256>>>(b2, hw, batch, out);

    cudaEventDestroy(eFork);
    cudaEventDestroy(eA);
    cudaEventDestroy(eB);
    cudaStreamDestroy(sA);
    cudaStreamDestroy(sB);
}